// round 5
// baseline (speedup 1.0000x reference)
#include <cuda_runtime.h>
#include <cuda_bf16.h>

#define Kdim 256
#define Ndim 65536
#define TT   32                  // fused tile width (time steps)
#define NT   (Ndim / TT)         // 2048 tiles

// ---------------- globals (no allocation) ------------------------------------
__device__ float  g_Mu0[Kdim];
__device__ double g_ll;

// ---------------- smem byte offsets ------------------------------------------
#define SOFF_A    0              // Alpha*Beta bf16, 256 rows x 512B, seg-XOR swizzled
#define SOFF_O0   131072         // obs tile fp32 [256 k][32 t], 32KB, seg-XOR swizzled
#define SOFF_O1   163840
#define SOFF_S    196608         // S bf16 [32 t][256 k], rows 512B, seg-XOR swizzled
#define SOFF_MU   212992
#define SOFF_RED  214016
#define SMEM_TOT  214144

// ---------------- Mu0 prepass (row means) ------------------------------------
__global__ __launch_bounds__(256) void k_mu0(const float* __restrict__ obs) {
    __shared__ float red[256];
    int k = blockIdx.x, t = threadIdx.x;
    if (k == 0 && t == 0) g_ll = 0.0;
    const float4* p = (const float4*)(obs + (size_t)k * Ndim);
    float s = 0.f;
    for (int i = t; i < Ndim / 4; i += 256) {
        float4 v = p[i];
        s += (v.x + v.y) + (v.z + v.w);
    }
    red[t] = s;
    __syncthreads();
    for (int o = 128; o > 0; o >>= 1) {
        if (t < o) red[t] += red[t + o];
        __syncthreads();
    }
    if (t == 0) g_Mu0[k] = red[0] * (1.0f / Ndim) * 0.1f + 0.01f;
}

// ---------------- helpers -----------------------------------------------------
__device__ __forceinline__ void mma16816(float* c, const unsigned* a, unsigned b0, unsigned b1) {
    asm volatile(
        "mma.sync.aligned.m16n8k16.row.col.f32.bf16.bf16.f32 "
        "{%0,%1,%2,%3}, {%4,%5,%6,%7}, {%8,%9}, {%0,%1,%2,%3};\n"
        : "+f"(c[0]), "+f"(c[1]), "+f"(c[2]), "+f"(c[3])
        : "r"(a[0]), "r"(a[1]), "r"(a[2]), "r"(a[3]), "r"(b0), "r"(b1));
}
__device__ __forceinline__ void ldmx4(unsigned& r0, unsigned& r1, unsigned& r2, unsigned& r3,
                                      unsigned addr) {
    asm volatile("ldmatrix.sync.aligned.m8n8.x4.shared.b16 {%0,%1,%2,%3}, [%4];"
                 : "=r"(r0), "=r"(r1), "=r"(r2), "=r"(r3) : "r"(addr));
}
__device__ __forceinline__ void cpa16(unsigned dst, const void* src) {
    asm volatile("cp.async.cg.shared.global [%0], [%1], 16;" :: "r"(dst), "l"(src));
}

// ---------------- fused scan + GEMM + epilogue (persistent CTAs) --------------
// Each CTA owns a contiguous tile range [t0,t1). Per tile:
//   1. obs[256][32] staged via cp.async (prefetched a tile ahead by warps 8-15)
//   2. warps 0-7 run the exponential-kernel recurrence (32 steps, state in regs,
//      warmup 32 steps at CTA start: decay<=e^-1 -> error ~1e-14 << bf16 eps),
//      writing bf16 S straight into smem in MMA-B layout [t][k]  (g_S deleted)
//   3. MMA: lam_z = (Alpha*Beta) @ S  from smem (A resident all kernel)
//   4. epilogue: softplus + lams stores straight from fragments (8 rows x 32B
//      sectors per STG instr); obs for loglik read from the staged smem block.
__global__ __launch_bounds__(512, 1) void k_main(
    const float* __restrict__ obs,
    const float* __restrict__ Alpha,
    const float* __restrict__ Beta,
    float* __restrict__ out)
{
    extern __shared__ __align__(16) char smem[];
    const unsigned su = (unsigned)__cvta_generic_to_shared(smem);
    float*  Mu0s = (float*)(smem + SOFF_MU);
    double* red  = (double*)(smem + SOFF_RED);

    const int tid = threadIdx.x, wid = tid >> 5, lane = tid & 31;
    const int G  = gridDim.x;
    const int t0 = (int)(((long)blockIdx.x * NT) / G);
    const int t1 = (int)(((long)(blockIdx.x + 1) * NT) / G);

    // ---- prologue: prefetch obs tile t0 -> O0 (all 512 threads, 4 segs each)
    #pragma unroll
    for (int ii = 0; ii < 4; ++ii) {
        int idx = tid + ii * 512;            // 0..2047: k = idx/8, seg = idx%8
        int k = idx >> 3, s = idx & 7;
        unsigned dst = su + SOFF_O0 + k * 128 + ((s ^ (k & 7)) << 4);
        cpa16(dst, (const char*)obs + ((size_t)k * Ndim + (size_t)t0 * TT + s * 4) * 4);
    }
    asm volatile("cp.async.commit_group;");

    // ---- stage Alpha*Beta -> swizzled bf16 smem [j][k] (rows 512B)
    {
        const float4* A4 = (const float4*)Alpha;
        const float4* B4 = (const float4*)Beta;
        for (int idx = tid; idx < 8192; idx += 512) {   // 16B chunks
            int j = idx >> 5, s = idx & 31;
            float4 v0 = A4[j * 64 + s * 2];
            float4 v1 = A4[j * 64 + s * 2 + 1];
            float4 b0 = __ldg(B4 + s * 2);
            float4 b1 = __ldg(B4 + s * 2 + 1);
            __nv_bfloat162 pk[4];
            pk[0] = __floats2bfloat162_rn(v0.x * b0.x, v0.y * b0.y);
            pk[1] = __floats2bfloat162_rn(v0.z * b0.z, v0.w * b0.w);
            pk[2] = __floats2bfloat162_rn(v1.x * b1.x, v1.y * b1.y);
            pk[3] = __floats2bfloat162_rn(v1.z * b1.z, v1.w * b1.w);
            int phys = (s & 24) | ((s & 7) ^ (j & 7));
            *(uint4*)(smem + SOFF_A + j * 512 + phys * 16) = *(uint4*)pk;
        }
        if (tid < 256) Mu0s[tid] = g_Mu0[tid];
    }

    // ---- scan state (thread k = tid, warps 0-7): warmup 32 steps from global
    float h = 0.f, prev = 0.f, decay = 0.f;
    if (tid < 256) {
        decay = __expf(-Beta[tid]);
        const int n0 = t0 * TT;
        if (n0 > 0) {
            const float* ow = obs + (size_t)tid * Ndim + n0 - 32;
            #pragma unroll
            for (int ii = 0; ii < 31; ++ii) h = decay * (h + __ldg(ow + ii));
            prev = __ldg(ow + 31);
        }
        // n0==0: h=0, prev=0 -> H(0)=0 exactly as reference requires.
    }

    // ---- precomputed MMA lane addressing
    const int wj = wid & 3;                       // 4 warps x 64 j
    const int wt = wid >> 2;                      // 4 warps x 8 t
    const int jsw  = lane & 7;
    const int subk = lane >> 4;
    unsigned ja[4];
    #pragma unroll
    for (int mf = 0; mf < 4; ++mf) {
        int jrow = wj * 64 + mf * 16 + (lane & 8) + (lane & 7);
        ja[mf] = su + SOFF_A + jrow * 512;
    }
    const int btr = wt * 8 + (lane & 7);          // B row (t)
    const int bsg = lane >> 3;                    // B seg-in-group 0..3
    const unsigned bb = su + SOFF_S + btr * 512;
    const int lg = lane >> 2, lm = lane & 3;

    float* lams0 = out + 1;
    float* lams1 = out + 1 + (size_t)Kdim * Ndim;
    const int ooff[2] = { SOFF_O0, SOFF_O1 };

    double lsum = 0.0;
    int p = 0;

    for (int tile = t0; tile < t1; ++tile, p ^= 1) {
        asm volatile("cp.async.wait_group 0;" ::: "memory");
        __syncthreads();   // obs[p] visible to all; S & obs[p^1] free (prev iter done)

        if (tid < 256) {
            // ---- scan this tile: obs[p] -> S (bf16, [t][k] swizzled)
            const float4* ob = (const float4*)(smem + ooff[p]);
            const int k8 = tid & 7, kq = tid >> 3;
            #pragma unroll
            for (int q = 0; q < 8; ++q) {
                float4 v = ob[tid * 8 + (q ^ k8)];
                float vv[4] = {v.x, v.y, v.z, v.w};
                #pragma unroll
                for (int r = 0; r < 4; ++r) {
                    const int t = q * 4 + r;
                    float dp = prev * decay;
                    h = __fmaf_rn(decay, h, dp);      // h = decay*(h + prev)
                    prev = vv[r];
                    const int phys = (kq & 24) | ((kq & 7) ^ (t & 7));
                    *(__nv_bfloat16*)(smem + SOFF_S + t * 512 + phys * 16 + k8 * 2) =
                        __float2bfloat16(h);
                }
            }
        } else {
            // ---- warps 8-15: prefetch next obs tile (overlaps the scan)
            if (tile + 1 < t1) {
                const int tn = tile + 1;
                #pragma unroll
                for (int ii = 0; ii < 8; ++ii) {
                    int idx = (tid - 256) + ii * 256;
                    int k = idx >> 3, s = idx & 7;
                    unsigned dst = su + ooff[p ^ 1] + k * 128 + ((s ^ (k & 7)) << 4);
                    cpa16(dst, (const char*)obs + ((size_t)k * Ndim + (size_t)tn * TT + s * 4) * 4);
                }
            }
            asm volatile("cp.async.commit_group;");
        }
        __syncthreads();   // S ready

        // ---- MMA: acc[mf][0..3] covers j16 x t8 per fragment
        float acc[4][4];
        #pragma unroll
        for (int a = 0; a < 4; ++a)
            #pragma unroll
            for (int d = 0; d < 4; ++d) acc[a][d] = 0.f;

        #pragma unroll
        for (int ks2 = 0; ks2 < 8; ++ks2) {
            const int seg = ks2 * 4 + bsg;
            unsigned b0, b1, b2, b3;
            ldmx4(b0, b1, b2, b3, bb + (((seg & 24) | ((seg & 7) ^ (btr & 7))) << 4));
            #pragma unroll
            for (int hh = 0; hh < 2; ++hh) {
                const int sA = 4 * ks2 + 2 * hh + subk;
                const unsigned aoff = (unsigned)(((sA & 24) | ((sA & 7) ^ jsw)) << 4);
                const unsigned bx = hh ? b2 : b0, by = hh ? b3 : b1;
                #pragma unroll
                for (int mf = 0; mf < 4; ++mf) {
                    unsigned a[4];
                    ldmx4(a[0], a[1], a[2], a[3], ja[mf] + aoff);
                    mma16816(acc[mf], a, bx, by);
                }
            }
        }

        // ---- epilogue straight from fragments (no extra sync needed)
        const float* obf = (const float*)(smem + ooff[p]);
        const int n0 = tile * TT;
        const int tl = wt * 8 + lm * 2;
        float fsum = 0.f;
        #pragma unroll
        for (int mf = 0; mf < 4; ++mf) {
            #pragma unroll
            for (int half = 0; half < 2; ++half) {
                const int j = wj * 64 + mf * 16 + lg + half * 8;
                float z0 = acc[mf][half * 2 + 0];
                float z1 = acc[mf][half * 2 + 1];
                float lam0 = z0 + __logf(1.f + __expf(-z0));   // softplus, z>=0
                float lam1 = z1 + __logf(1.f + __expf(-z1));
                const int n = n0 + tl;
                if (n == 0) lam0 = 0.f;          // reference: lams1[:,0] = 0
                const float mu = Mu0s[j];
                const size_t base = (size_t)j * Ndim + n;
                lams1[base]     = lam0;          // out+1 is 4B-aligned -> scalar STG
                lams1[base + 1] = lam1;
                lams0[base]     = mu;
                lams0[base + 1] = mu;
                float2 ov = *(const float2*)&obf[j * 32 + (((tl >> 2) ^ (j & 7)) << 2) + (tl & 3)];
                fsum += ov.x * __logf(mu + lam0 + 1e-5f) - mu - lam0;
                fsum += ov.y * __logf(mu + lam1 + 1e-5f) - mu - lam1;
            }
        }
        lsum += (double)fsum;
    }

    // ---- loglik reduction: shuffle -> smem -> one atomicAdd per CTA
    #pragma unroll
    for (int o = 16; o > 0; o >>= 1)
        lsum += __shfl_down_sync(0xffffffffu, lsum, o);
    if (lane == 0) red[wid] = lsum;
    __syncthreads();
    if (tid == 0) {
        double s = 0.0;
        #pragma unroll
        for (int i = 0; i < 16; ++i) s += red[i];
        atomicAdd(&g_ll, s);
    }
}

__global__ void k_final(float* __restrict__ out) { out[0] = (float)g_ll; }

// ---------------- launch ------------------------------------------------------
extern "C" void kernel_launch(void* const* d_in, const int* in_sizes, int n_in,
                              void* d_out, int out_size) {
    const float* obs   = (const float*)d_in[0];
    const float* Beta  = (const float*)d_in[1];
    const float* Alpha = (const float*)d_in[2];
    float* out = (float*)d_out;

    k_mu0<<<Kdim, 256>>>(obs);

    cudaFuncSetAttribute(k_main, cudaFuncAttributeMaxDynamicSharedMemorySize, SMEM_TOT);
    int nsm = 148;
    cudaDeviceGetAttribute(&nsm, cudaDevAttrMultiProcessorCount, 0);
    k_main<<<nsm, 512, SMEM_TOT>>>(obs, Alpha, Beta, out);

    k_final<<<1, 1>>>(out);
}

// round 7
// speedup vs baseline: 1.2914x; 1.2914x over previous
#include <cuda_runtime.h>
#include <cuda_bf16.h>

#define Kdim 256
#define Ndim 65536
#define TT   64                  // GEMM time-tile width
#define NT   (Ndim / TT)         // 1024
#define CHUNKS 512               // scan chunks per row (128 steps each)

// ---------------- scratch (static device globals; no allocation) -------------
__device__ __nv_bfloat16 g_S[(size_t)Kdim * Ndim];   // [tile64][k][64] bf16
__device__ float  g_psum[Kdim * CHUNKS];
__device__ float  g_Mu0[Kdim];
__device__ double g_ll;
__device__ int    g_done;

// ---------------- scan: truncated exponential-kernel recursion ---------------
// H(i) = decay*(H(i-1)+obs[k][i-1]); decay <= e^-1 -> 32-step warmup error
// ~1e-14 << bf16 eps. Fully smem-staged: all global traffic coalesced.
__global__ __launch_bounds__(128) void k_scan(const float* __restrict__ obs,
                                              const float* __restrict__ Beta) {
    extern __shared__ __align__(16) char sm[];
    float* obs_s = (float*)sm;                       // 128 chunks x 132 floats
    uint4* out_s = (uint4*)(sm + 128 * 132 * 4);     // 128 chunks x 16 uint4 (swizzled)

    const int tid = threadIdx.x;
    const int k   = blockIdx.x >> 2;
    const int qtr = blockIdx.x & 3;
    if (blockIdx.x == 0 && tid == 0) { g_ll = 0.0; g_done = 0; }
    const float4* orow4 = (const float4*)(obs + (size_t)k * Ndim) + qtr * 4096;

    #pragma unroll
    for (int i = 0; i < 32; ++i) {
        float4 v = __ldg(orow4 + i * 128 + tid);
        int c = i * 4 + (tid >> 5);
        int w = (tid & 31) * 4;
        *(float4*)&obs_s[c * 132 + w] = v;
    }
    __syncthreads();

    const float decay = __expf(-Beta[k]);

    float h = 0.f, prev = 0.f;
    if (tid > 0) {
        const float* wsrc = &obs_s[(tid - 1) * 132 + 96];
        #pragma unroll
        for (int j = 0; j < 8; ++j) {
            float4 f = *(const float4*)(wsrc + j * 4);
            h = decay * (h + f.x);
            h = decay * (h + f.y);
            h = decay * (h + f.z);
            if (j < 7) h = decay * (h + f.w); else prev = f.w;
        }
    } else if (qtr > 0) {
        const float4* g = (const float4*)(obs + (size_t)k * Ndim + qtr * 16384 - 32);
        #pragma unroll
        for (int j = 0; j < 8; ++j) {
            float4 f = __ldg(g + j);
            h = decay * (h + f.x);
            h = decay * (h + f.y);
            h = decay * (h + f.z);
            if (j < 7) h = decay * (h + f.w); else prev = f.w;
        }
    }
    // qtr==0 && tid==0: h=0, prev=0 -> H(0)=0 exactly as reference requires.

    float sum = 0.f;
    const float* src = &obs_s[tid * 132];
    #pragma unroll
    for (int q = 0; q < 16; ++q) {
        float4 a = *(const float4*)(src + q * 8);
        float4 b = *(const float4*)(src + q * 8 + 4);
        float v[8] = {a.x, a.y, a.z, a.w, b.x, b.y, b.z, b.w};
        __nv_bfloat162 p[4];
        #pragma unroll
        for (int r = 0; r < 8; r += 2) {
            h = decay * (h + prev); float h0 = h; prev = v[r];
            h = decay * (h + prev); float h1 = h; prev = v[r + 1];
            p[r >> 1] = __floats2bfloat162_rn(h0, h1);
            sum += v[r] + v[r + 1];
        }
        out_s[tid * 16 + (q ^ (tid & 15))] = *(uint4*)p;
    }
    g_psum[k * CHUNKS + qtr * 128 + tid] = sum;
    __syncthreads();

    uint4* g4 = (uint4*)g_S;
    #pragma unroll
    for (int j = 0; j < 16; ++j) {
        int idx = j * 128 + tid;
        int gc = idx >> 4, qq = idx & 15;
        uint4 v = out_s[gc * 16 + (qq ^ (gc & 15))];
        int tile = (qtr * 128 + gc) * 2 + (qq >> 3);
        g4[((size_t)tile * Kdim + k) * 8 + (qq & 7)] = v;
    }
}

// ---------------- Mu0 reduction (deterministic fixed-order tree) -------------
__global__ void k_mu0(void) {
    __shared__ float red[128];
    int k = blockIdx.x, t = threadIdx.x;
    const float* p = g_psum + k * CHUNKS;
    float s = p[t] + p[t + 128] + p[t + 256] + p[t + 384];
    red[t] = s;
    __syncthreads();
    for (int o = 64; o > 0; o >>= 1) {
        if (t < o) red[t] += red[t + o];
        __syncthreads();
    }
    if (t == 0) g_Mu0[k] = red[0] * (1.0f / Ndim) * 0.1f + 0.01f;
}

// ---------------- mma / ldmatrix helpers -------------------------------------
__device__ __forceinline__ void mma16816(float* c, const unsigned* a, unsigned b0, unsigned b1) {
    asm volatile(
        "mma.sync.aligned.m16n8k16.row.col.f32.bf16.bf16.f32 "
        "{%0,%1,%2,%3}, {%4,%5,%6,%7}, {%8,%9}, {%0,%1,%2,%3};\n"
        : "+f"(c[0]), "+f"(c[1]), "+f"(c[2]), "+f"(c[3])
        : "r"(a[0]), "r"(a[1]), "r"(a[2]), "r"(a[3]), "r"(b0), "r"(b1));
}
__device__ __forceinline__ void ldmx4(unsigned& r0, unsigned& r1, unsigned& r2, unsigned& r3,
                                      unsigned addr) {
    asm volatile("ldmatrix.sync.aligned.m8n8.x4.shared.b16 {%0,%1,%2,%3}, [%4];"
                 : "=r"(r0), "=r"(r1), "=r"(r2), "=r"(r3) : "r"(addr));
}
__device__ __forceinline__ void ldmx4t(unsigned& r0, unsigned& r1, unsigned& r2, unsigned& r3,
                                       unsigned addr) {
    asm volatile("ldmatrix.sync.aligned.m8n8.x4.trans.shared.b16 {%0,%1,%2,%3}, [%4];"
                 : "=r"(r0), "=r"(r1), "=r"(r2), "=r"(r3) : "r"(addr));
}
__device__ __forceinline__ void cpa16(unsigned dst, const void* src) {
    asm volatile("cp.async.cg.shared.global [%0], [%1], 16;" :: "r"(dst), "l"(src));
}

// smem byte offsets for k_gemm
#define SOFF_A   0               // 256 x 512B (Alpha*Beta bf16, seg-XOR swizzled)
#define SOFF_S0  131072          // S tile buf 0: 256 k-rows x 128B (64 t bf16)
#define SOFF_S1  163840          // S tile buf 1
#define SOFF_MU  196608
#define SOFF_RED 197632          // 32 doubles
#define SMEM_TOT 197888

// ---------------- fused GEMM (lam1 = softplus((Alpha*Beta) @ H)) + epilogue --
// 1024 threads, 32 warps (4 j-warps x 64 rows, 8 t-warps x 8 cols). Persistent
// CTAs; A resident in smem; S tiles double-buffered via cp.async; B via
// ldmatrix.trans; epilogue bounces acc through the consumed S buffer so all
// lams/obs global traffic is 128B-coalesced. Final scalar folded in via a
// completion counter.
__global__ __launch_bounds__(1024, 1) void k_gemm(
    const float* __restrict__ obs,
    const float* __restrict__ Alpha,
    const float* __restrict__ Beta,
    float* __restrict__ out)
{
    extern __shared__ __align__(16) char smem[];
    const unsigned su = (unsigned)__cvta_generic_to_shared(smem);
    float*  Mu0s = (float*)(smem + SOFF_MU);
    double* red  = (double*)(smem + SOFF_RED);

    const int tid = threadIdx.x, wid = tid >> 5, lane = tid & 31;
    const int wj = wid & 3;                 // 4 warps x 64 j
    const int wt = wid >> 2;                // 8 warps x 8 t
    const int jsw = lane & 7, subk = lane >> 4;
    const int lg = lane >> 2, lm = lane & 3;

    // ---- prefetch tile(blockIdx) -> buf0
    {
        const char* src = (const char*)g_S + (size_t)blockIdx.x * 32768;
        #pragma unroll
        for (int i = 0; i < 2; ++i) {
            int idx = tid + i * 1024;       // 0..2047
            int k = idx >> 3, s = idx & 7;
            cpa16(su + SOFF_S0 + k * 128 + ((s ^ (k & 7)) << 4), src + idx * 16);
        }
        asm volatile("cp.async.commit_group;");
    }

    // ---- stage Alpha*Beta -> swizzled bf16 smem [j][k] (rows 512B)
    {
        const float4* A4 = (const float4*)Alpha;
        const float4* B4 = (const float4*)Beta;
        #pragma unroll
        for (int ii = 0; ii < 8; ++ii) {
            int idx = tid + ii * 1024;      // 16B chunks, 0..8191
            int j = idx >> 5, s = idx & 31;
            float4 v0 = A4[j * 64 + s * 2];
            float4 v1 = A4[j * 64 + s * 2 + 1];
            float4 b0 = __ldg(B4 + s * 2);
            float4 b1 = __ldg(B4 + s * 2 + 1);
            __nv_bfloat162 pk[4];
            pk[0] = __floats2bfloat162_rn(v0.x * b0.x, v0.y * b0.y);
            pk[1] = __floats2bfloat162_rn(v0.z * b0.z, v0.w * b0.w);
            pk[2] = __floats2bfloat162_rn(v1.x * b1.x, v1.y * b1.y);
            pk[3] = __floats2bfloat162_rn(v1.z * b1.z, v1.w * b1.w);
            int phys = (s & 24) | ((s & 7) ^ (j & 7));
            *(uint4*)(smem + SOFF_A + j * 512 + phys * 16) = *(uint4*)pk;
        }
        if (tid < 256) Mu0s[tid] = g_Mu0[tid];
    }

    // ---- precomputed lane addresses
    unsigned ja[4];
    #pragma unroll
    for (int mf = 0; mf < 4; ++mf) {
        int jrow = wj * 64 + mf * 16 + (lane & 8) + jsw;
        ja[mf] = su + SOFF_A + jrow * 512;
    }
    const unsigned boff = (unsigned)(lane * 128 + ((wt ^ jsw) << 4));

    float* lams0 = out + 1;
    float* lams1 = out + 1 + (size_t)Kdim * Ndim;

    double lsum = 0.0;
    int p = 0;

    for (int tile = blockIdx.x; tile < NT; tile += gridDim.x, p ^= 1) {
        asm volatile("cp.async.wait_group 0;" ::: "memory");
        __syncthreads();                    // buf[p] ready; buf[p^1]+bounce free

        // ---- MMA
        float acc[4][4];
        #pragma unroll
        for (int a = 0; a < 4; ++a)
            #pragma unroll
            for (int d = 0; d < 4; ++d) acc[a][d] = 0.f;

        const unsigned bb = su + (p ? SOFF_S1 : SOFF_S0) + boff;
        #pragma unroll
        for (int ks2 = 0; ks2 < 8; ++ks2) {
            unsigned b0, b1, b2, b3;
            ldmx4t(b0, b1, b2, b3, bb + ks2 * 4096);
            #pragma unroll
            for (int hh = 0; hh < 2; ++hh) {
                const int sA = (ks2 * 2 + hh) * 2 + subk;
                const unsigned aoff = (unsigned)(((sA & 24) | ((sA & 7) ^ jsw)) << 4);
                const unsigned bx = hh ? b2 : b0, by = hh ? b3 : b1;
                #pragma unroll
                for (int mf = 0; mf < 4; ++mf) {
                    unsigned a[4];
                    ldmx4(a[0], a[1], a[2], a[3], ja[mf] + aoff);
                    mma16816(acc[mf], a, bx, by);
                }
            }
        }
        __syncthreads();                    // all warps done reading buf[p]

        // ---- prefetch next tile into buf[p^1] (overlaps epilogue)
        {
            int nxt = tile + gridDim.x;
            if (nxt < NT) {
                const char* src = (const char*)g_S + (size_t)nxt * 32768;
                #pragma unroll
                for (int i = 0; i < 2; ++i) {
                    int idx = tid + i * 1024;
                    int k = idx >> 3, s = idx & 7;
                    cpa16(su + (p ? SOFF_S0 : SOFF_S1) + k * 128 + ((s ^ (k & 7)) << 4),
                          src + idx * 16);
                }
            }
            asm volatile("cp.async.commit_group;");
        }

        // ---- epilogue: 2 j-slices of 128 rows, bounced through buf[p]
        float*  Sf  = (float*)(smem + (p ? SOFF_S1 : SOFF_S0));  // [128][64] XOR
        float2* Sf2 = (float2*)Sf;
        const int n0 = tile * TT;

        #pragma unroll
        for (int s = 0; s < 2; ++s) {
            if ((wj >> 1) == s) {
                #pragma unroll
                for (int mf = 0; mf < 4; ++mf)
                    #pragma unroll
                    for (int half = 0; half < 2; ++half) {
                        const int jl = (wj & 1) * 64 + mf * 16 + lg + half * 8;
                        const int gsw = wt ^ (jl & 7);
                        Sf2[jl * 32 + gsw * 4 + lm] =
                            make_float2(acc[mf][half * 2], acc[mf][half * 2 + 1]);
                    }
            }
            __syncthreads();

            float fsum = 0.f;
            #pragma unroll
            for (int rr = 0; rr < 4; ++rr) {
                const int jl = wid * 4 + rr;
                const int jg = s * 128 + jl;
                const float mu = Mu0s[jg];
                const size_t rowbase = (size_t)jg * Ndim + n0;
                #pragma unroll
                for (int pass = 0; pass < 2; ++pass) {
                    const int tof = pass * 32 + lane;
                    float z = Sf[jl * 64 + (((tof >> 3) ^ (jl & 7)) << 3) + (tof & 7)];
                    float lam = z + __logf(1.f + __expf(-z));   // softplus, z>=0
                    if (n0 + tof == 0) lam = 0.f;   // reference: lams1[:,0] = 0
                    const size_t base = rowbase + tof;
                    lams1[base] = lam;
                    lams0[base] = mu;
                    float o = __ldg(obs + base);
                    fsum += o * __logf(mu + lam + 1e-5f) - mu - lam;
                }
            }
            lsum += (double)fsum;
            __syncthreads();
        }
    }
    asm volatile("cp.async.wait_group 0;" ::: "memory");   // drain tail prefetch

    // ---- loglik reduction + folded final write
    #pragma unroll
    for (int o = 16; o > 0; o >>= 1)
        lsum += __shfl_down_sync(0xffffffffu, lsum, o);
    if (lane == 0) red[wid] = lsum;
    __syncthreads();
    if (tid == 0) {
        double s = 0.0;
        #pragma unroll
        for (int i = 0; i < 32; ++i) s += red[i];
        atomicAdd(&g_ll, s);
        __threadfence();
        int done = atomicAdd(&g_done, 1);
        if (done == gridDim.x - 1) {
            out[0] = (float)atomicAdd(&g_ll, 0.0);   // coherent read of final sum
            g_done = 0;                              // reset for next graph replay
        }
    }
}

// ---------------- launch ------------------------------------------------------
extern "C" void kernel_launch(void* const* d_in, const int* in_sizes, int n_in,
                              void* d_out, int out_size) {
    const float* obs   = (const float*)d_in[0];
    const float* Beta  = (const float*)d_in[1];
    const float* Alpha = (const float*)d_in[2];
    float* out = (float*)d_out;

    const int scan_smem = 128 * 132 * 4 + 128 * 16 * 16;   // 100352 B
    cudaFuncSetAttribute(k_scan, cudaFuncAttributeMaxDynamicSharedMemorySize, scan_smem);
    k_scan<<<Kdim * 4, 128, scan_smem>>>(obs, Beta);

    k_mu0<<<Kdim, 128>>>();

    cudaFuncSetAttribute(k_gemm, cudaFuncAttributeMaxDynamicSharedMemorySize, SMEM_TOT);
    int nsm = 148;
    cudaDeviceGetAttribute(&nsm, cudaDevAttrMultiProcessorCount, 0);
    k_gemm<<<nsm, 1024, SMEM_TOT>>>(obs, Alpha, Beta, out);
}

// round 8
// speedup vs baseline: 1.3658x; 1.0576x over previous
#include <cuda_runtime.h>
#include <cuda_bf16.h>

#define Kdim 256
#define Ndim 65536
#define TT   64                  // GEMM time-tile width
#define NT   (Ndim / TT)         // 1024

// ---------------- scratch (static device globals; no allocation) -------------
__device__ __nv_bfloat16 g_S[(size_t)Kdim * Ndim];   // [tile64][k][64] bf16
__device__ float  g_psum[Kdim * 4];
__device__ float  g_Mu0[Kdim];
__device__ double g_ll;
__device__ int    g_done;

// ---------------- scan: truncated exponential-kernel recursion ---------------
// H(i) = decay*(H(i-1)+obs[k][i-1]); decay <= e^-1 -> 32-step warmup error
// ~1e-14 << bf16 eps. 256 threads/block, 64-step chunks (one TT tile each):
// serial FFMA chain is 512 cycles and 16 warps/SM hide it. All global traffic
// coalesced via smem staging / bounce.
__global__ __launch_bounds__(256) void k_scan(const float* __restrict__ obs,
                                              const float* __restrict__ Beta) {
    extern __shared__ __align__(16) char sm[];
    float* obs_s = (float*)sm;                       // 256 chunks x 68 floats
    uint4* out_s = (uint4*)(sm + 256 * 68 * 4);      // 256 chunks x 8 uint4 (swizzled)
    float* redp  = (float*)(sm + 256 * 68 * 4);      // reused after out drained? NO:
                                                     // psum uses its own tail slot
    float* psr   = (float*)(sm + 256 * 68 * 4 + 256 * 8 * 16);  // 64 floats

    const int tid = threadIdx.x;
    const int k   = blockIdx.x >> 2;
    const int qtr = blockIdx.x & 3;
    if (blockIdx.x == 0 && tid == 0) { g_ll = 0.0; g_done = 0; }
    const float4* orow4 = (const float4*)(obs + (size_t)k * Ndim) + qtr * 4096;

    // ---- stage 64KB of obs (quarter row), coalesced, into chunk-padded smem
    #pragma unroll
    for (int i = 0; i < 16; ++i) {
        int idx = i * 256 + tid;             // float4 id, 0..4095
        float4 v = __ldg(orow4 + idx);
        int c = idx >> 4, w = idx & 15;
        *(float4*)&obs_s[c * 68 + w * 4] = v;
    }
    __syncthreads();

    const float decay = __expf(-Beta[k]);

    // ---- warmup over obs[n0-32 .. n0-1]  (last value becomes `prev`)
    float h = 0.f, prev = 0.f;
    if (tid > 0) {
        const float* wsrc = &obs_s[(tid - 1) * 68 + 32];
        #pragma unroll
        for (int j = 0; j < 8; ++j) {
            float4 f = *(const float4*)(wsrc + j * 4);
            h = decay * (h + f.x);
            h = decay * (h + f.y);
            h = decay * (h + f.z);
            if (j < 7) h = decay * (h + f.w); else prev = f.w;
        }
    } else if (qtr > 0) {
        const float4* g = (const float4*)(obs + (size_t)k * Ndim + qtr * 16384 - 32);
        #pragma unroll
        for (int j = 0; j < 8; ++j) {
            float4 f = __ldg(g + j);
            h = decay * (h + f.x);
            h = decay * (h + f.y);
            h = decay * (h + f.z);
            if (j < 7) h = decay * (h + f.w); else prev = f.w;
        }
    }
    // qtr==0 && tid==0: h=0, prev=0 -> H(0)=0 exactly as reference requires.

    // ---- recurrence over this thread's 64-step chunk (== one tile row)
    float sum = 0.f;
    const float* src = &obs_s[tid * 68];
    #pragma unroll
    for (int q = 0; q < 8; ++q) {
        float4 a = *(const float4*)(src + q * 8);
        float4 b = *(const float4*)(src + q * 8 + 4);
        float v[8] = {a.x, a.y, a.z, a.w, b.x, b.y, b.z, b.w};
        __nv_bfloat162 p[4];
        #pragma unroll
        for (int r = 0; r < 8; r += 2) {
            h = decay * (h + prev); float h0 = h; prev = v[r];
            h = decay * (h + prev); float h1 = h; prev = v[r + 1];
            p[r >> 1] = __floats2bfloat162_rn(h0, h1);
            sum += v[r] + v[r + 1];
        }
        out_s[tid * 8 + (q ^ (tid & 7))] = *(uint4*)p;   // XOR-swizzled store
    }

    // ---- block-reduce quarter-row sum -> one psum per block
    #pragma unroll
    for (int o = 16; o > 0; o >>= 1)
        sum += __shfl_down_sync(0xffffffffu, sum, o);
    if ((tid & 31) == 0) psr[tid >> 5] = sum;
    __syncthreads();
    if (tid == 0) {
        float s = 0.f;
        #pragma unroll
        for (int i = 0; i < 8; ++i) s += psr[i];
        g_psum[k * 4 + qtr] = s;
    }

    // ---- cooperative coalesced store into [tile64][k][64] blocks
    uint4* g4 = (uint4*)g_S;
    #pragma unroll
    for (int j = 0; j < 8; ++j) {
        int idx = j * 256 + tid;             // 0..2047
        int gc = idx >> 3, qq = idx & 7;
        uint4 v = out_s[gc * 8 + (qq ^ (gc & 7))];
        int tile = qtr * 256 + gc;
        g4[((size_t)tile * Kdim + k) * 8 + qq] = v;
    }
}

// ---------------- Mu0: one tiny block -----------------------------------------
__global__ void k_mu0(void) {
    int k = threadIdx.x;
    const float* p = g_psum + k * 4;
    g_Mu0[k] = ((p[0] + p[1]) + (p[2] + p[3])) * (1.0f / Ndim) * 0.1f + 0.01f;
}

// ---------------- mma / ldmatrix helpers -------------------------------------
__device__ __forceinline__ void mma16816(float* c, const unsigned* a, unsigned b0, unsigned b1) {
    asm volatile(
        "mma.sync.aligned.m16n8k16.row.col.f32.bf16.bf16.f32 "
        "{%0,%1,%2,%3}, {%4,%5,%6,%7}, {%8,%9}, {%0,%1,%2,%3};\n"
        : "+f"(c[0]), "+f"(c[1]), "+f"(c[2]), "+f"(c[3])
        : "r"(a[0]), "r"(a[1]), "r"(a[2]), "r"(a[3]), "r"(b0), "r"(b1));
}
__device__ __forceinline__ void ldmx4(unsigned& r0, unsigned& r1, unsigned& r2, unsigned& r3,
                                      unsigned addr) {
    asm volatile("ldmatrix.sync.aligned.m8n8.x4.shared.b16 {%0,%1,%2,%3}, [%4];"
                 : "=r"(r0), "=r"(r1), "=r"(r2), "=r"(r3) : "r"(addr));
}
__device__ __forceinline__ void ldmx4t(unsigned& r0, unsigned& r1, unsigned& r2, unsigned& r3,
                                       unsigned addr) {
    asm volatile("ldmatrix.sync.aligned.m8n8.x4.trans.shared.b16 {%0,%1,%2,%3}, [%4];"
                 : "=r"(r0), "=r"(r1), "=r"(r2), "=r"(r3) : "r"(addr));
}
__device__ __forceinline__ void cpa16(unsigned dst, const void* src) {
    asm volatile("cp.async.cg.shared.global [%0], [%1], 16;" :: "r"(dst), "l"(src));
}

// smem byte offsets for k_gemm
#define SOFF_A   0               // 256 x 512B (Alpha*Beta bf16, seg-XOR swizzled)
#define SOFF_S0  131072          // S tile buf 0: 256 k-rows x 128B (64 t bf16)
#define SOFF_S1  163840          // S tile buf 1
#define SOFF_MU  196608
#define SOFF_RED 197632          // 32 doubles
#define SMEM_TOT 197888

// ---------------- fused GEMM (lam1 = softplus((Alpha*Beta) @ H)) + epilogue --
// 1024 threads, 32 warps (4 j-warps x 64 rows, 8 t-warps x 8 cols). Persistent
// CTAs; A resident in smem; S tiles double-buffered via cp.async; B via
// ldmatrix.trans; epilogue bounces acc through the consumed S buffer so all
// lams/obs global traffic is 128B-coalesced. Final scalar folded in via a
// completion counter.
__global__ __launch_bounds__(1024, 1) void k_gemm(
    const float* __restrict__ obs,
    const float* __restrict__ Alpha,
    const float* __restrict__ Beta,
    float* __restrict__ out)
{
    extern __shared__ __align__(16) char smem[];
    const unsigned su = (unsigned)__cvta_generic_to_shared(smem);
    float*  Mu0s = (float*)(smem + SOFF_MU);
    double* red  = (double*)(smem + SOFF_RED);

    const int tid = threadIdx.x, wid = tid >> 5, lane = tid & 31;
    const int wj = wid & 3;                 // 4 warps x 64 j
    const int wt = wid >> 2;                // 8 warps x 8 t
    const int jsw = lane & 7, subk = lane >> 4;
    const int lg = lane >> 2, lm = lane & 3;

    // ---- prefetch tile(blockIdx) -> buf0
    {
        const char* src = (const char*)g_S + (size_t)blockIdx.x * 32768;
        #pragma unroll
        for (int i = 0; i < 2; ++i) {
            int idx = tid + i * 1024;       // 0..2047
            int k = idx >> 3, s = idx & 7;
            cpa16(su + SOFF_S0 + k * 128 + ((s ^ (k & 7)) << 4), src + idx * 16);
        }
        asm volatile("cp.async.commit_group;");
    }

    // ---- stage Alpha*Beta -> swizzled bf16 smem [j][k] (rows 512B)
    {
        const float4* A4 = (const float4*)Alpha;
        const float4* B4 = (const float4*)Beta;
        #pragma unroll
        for (int ii = 0; ii < 8; ++ii) {
            int idx = tid + ii * 1024;      // 16B chunks, 0..8191
            int j = idx >> 5, s = idx & 31;
            float4 v0 = A4[j * 64 + s * 2];
            float4 v1 = A4[j * 64 + s * 2 + 1];
            float4 b0 = __ldg(B4 + s * 2);
            float4 b1 = __ldg(B4 + s * 2 + 1);
            __nv_bfloat162 pk[4];
            pk[0] = __floats2bfloat162_rn(v0.x * b0.x, v0.y * b0.y);
            pk[1] = __floats2bfloat162_rn(v0.z * b0.z, v0.w * b0.w);
            pk[2] = __floats2bfloat162_rn(v1.x * b1.x, v1.y * b1.y);
            pk[3] = __floats2bfloat162_rn(v1.z * b1.z, v1.w * b1.w);
            int phys = (s & 24) | ((s & 7) ^ (j & 7));
            *(uint4*)(smem + SOFF_A + j * 512 + phys * 16) = *(uint4*)pk;
        }
        if (tid < 256) Mu0s[tid] = g_Mu0[tid];
    }

    // ---- precomputed lane addresses
    unsigned ja[4];
    #pragma unroll
    for (int mf = 0; mf < 4; ++mf) {
        int jrow = wj * 64 + mf * 16 + (lane & 8) + jsw;
        ja[mf] = su + SOFF_A + jrow * 512;
    }
    const unsigned boff = (unsigned)(lane * 128 + ((wt ^ jsw) << 4));

    float* lams0 = out + 1;
    float* lams1 = out + 1 + (size_t)Kdim * Ndim;

    double lsum = 0.0;
    int p = 0;

    for (int tile = blockIdx.x; tile < NT; tile += gridDim.x, p ^= 1) {
        asm volatile("cp.async.wait_group 0;" ::: "memory");
        __syncthreads();                    // buf[p] ready; buf[p^1]+bounce free

        // ---- MMA
        float acc[4][4];
        #pragma unroll
        for (int a = 0; a < 4; ++a)
            #pragma unroll
            for (int d = 0; d < 4; ++d) acc[a][d] = 0.f;

        const unsigned bb = su + (p ? SOFF_S1 : SOFF_S0) + boff;
        #pragma unroll
        for (int ks2 = 0; ks2 < 8; ++ks2) {
            unsigned b0, b1, b2, b3;
            ldmx4t(b0, b1, b2, b3, bb + ks2 * 4096);
            #pragma unroll
            for (int hh = 0; hh < 2; ++hh) {
                const int sA = (ks2 * 2 + hh) * 2 + subk;
                const unsigned aoff = (unsigned)(((sA & 24) | ((sA & 7) ^ jsw)) << 4);
                const unsigned bx = hh ? b2 : b0, by = hh ? b3 : b1;
                #pragma unroll
                for (int mf = 0; mf < 4; ++mf) {
                    unsigned a[4];
                    ldmx4(a[0], a[1], a[2], a[3], ja[mf] + aoff);
                    mma16816(acc[mf], a, bx, by);
                }
            }
        }
        __syncthreads();                    // all warps done reading buf[p]

        // ---- prefetch next tile into buf[p^1] (overlaps epilogue)
        {
            int nxt = tile + gridDim.x;
            if (nxt < NT) {
                const char* src = (const char*)g_S + (size_t)nxt * 32768;
                #pragma unroll
                for (int i = 0; i < 2; ++i) {
                    int idx = tid + i * 1024;
                    int k = idx >> 3, s = idx & 7;
                    cpa16(su + (p ? SOFF_S0 : SOFF_S1) + k * 128 + ((s ^ (k & 7)) << 4),
                          src + idx * 16);
                }
            }
            asm volatile("cp.async.commit_group;");
        }

        // ---- epilogue: 2 j-slices of 128 rows, bounced through buf[p]
        float*  Sf  = (float*)(smem + (p ? SOFF_S1 : SOFF_S0));  // [128][64] XOR
        float2* Sf2 = (float2*)Sf;
        const int n0 = tile * TT;

        #pragma unroll
        for (int s = 0; s < 2; ++s) {
            if ((wj >> 1) == s) {
                #pragma unroll
                for (int mf = 0; mf < 4; ++mf)
                    #pragma unroll
                    for (int half = 0; half < 2; ++half) {
                        const int jl = (wj & 1) * 64 + mf * 16 + lg + half * 8;
                        const int gsw = wt ^ (jl & 7);
                        Sf2[jl * 32 + gsw * 4 + lm] =
                            make_float2(acc[mf][half * 2], acc[mf][half * 2 + 1]);
                    }
            }
            __syncthreads();

            float fsum = 0.f;
            #pragma unroll
            for (int rr = 0; rr < 4; ++rr) {
                const int jl = wid * 4 + rr;
                const int jg = s * 128 + jl;
                const float mu = Mu0s[jg];
                const size_t rowbase = (size_t)jg * Ndim + n0;
                #pragma unroll
                for (int pass = 0; pass < 2; ++pass) {
                    const int tof = pass * 32 + lane;
                    float z = Sf[jl * 64 + (((tof >> 3) ^ (jl & 7)) << 3) + (tof & 7)];
                    float lam = z + __logf(1.f + __expf(-z));   // softplus, z>=0
                    if (n0 + tof == 0) lam = 0.f;   // reference: lams1[:,0] = 0
                    const size_t base = rowbase + tof;
                    lams1[base] = lam;
                    lams0[base] = mu;
                    float o = __ldg(obs + base);
                    fsum += o * __logf(mu + lam + 1e-5f) - mu - lam;
                }
            }
            lsum += (double)fsum;
            __syncthreads();
        }
    }
    asm volatile("cp.async.wait_group 0;" ::: "memory");   // drain tail prefetch

    // ---- loglik reduction + folded final write
    #pragma unroll
    for (int o = 16; o > 0; o >>= 1)
        lsum += __shfl_down_sync(0xffffffffu, lsum, o);
    if (lane == 0) red[wid] = lsum;
    __syncthreads();
    if (tid == 0) {
        double s = 0.0;
        #pragma unroll
        for (int i = 0; i < 32; ++i) s += red[i];
        atomicAdd(&g_ll, s);
        __threadfence();
        int done = atomicAdd(&g_done, 1);
        if (done == gridDim.x - 1) {
            out[0] = (float)atomicAdd(&g_ll, 0.0);   // coherent read of final sum
            g_done = 0;                              // reset for next graph replay
        }
    }
}

// ---------------- launch ------------------------------------------------------
extern "C" void kernel_launch(void* const* d_in, const int* in_sizes, int n_in,
                              void* d_out, int out_size) {
    const float* obs   = (const float*)d_in[0];
    const float* Beta  = (const float*)d_in[1];
    const float* Alpha = (const float*)d_in[2];
    float* out = (float*)d_out;

    const int scan_smem = 256 * 68 * 4 + 256 * 8 * 16 + 64 * 4;   // 102656 B
    cudaFuncSetAttribute(k_scan, cudaFuncAttributeMaxDynamicSharedMemorySize, scan_smem);
    k_scan<<<Kdim * 4, 256, scan_smem>>>(obs, Beta);

    k_mu0<<<1, Kdim>>>();

    cudaFuncSetAttribute(k_gemm, cudaFuncAttributeMaxDynamicSharedMemorySize, SMEM_TOT);
    int nsm = 148;
    cudaDeviceGetAttribute(&nsm, cudaDevAttrMultiProcessorCount, 0);
    k_gemm<<<nsm, 1024, SMEM_TOT>>>(obs, Alpha, Beta, out);
}

// round 9
// speedup vs baseline: 1.5436x; 1.1302x over previous
#include <cuda_runtime.h>
#include <cuda_bf16.h>

#define Kdim 256
#define Ndim 65536
#define TT   64                  // GEMM time-tile width
#define NT   (Ndim / TT)         // 1024

// ---------------- scratch (static device globals; no allocation) -------------
__device__ __nv_bfloat16 g_S[(size_t)Kdim * Ndim];   // [tile64][k][64] bf16
__device__ float  g_psum[Kdim * 4];
__device__ double g_ll;
__device__ int    g_done;

// ---------------- scan: truncated exponential-kernel recursion ---------------
// H(i) = decay*(H(i-1)+obs[k][i-1]) == fma(decay, H, decay*obs) -> 4cyc chain.
// decay <= e^-1 -> 32-step warmup error ~1e-14 << bf16 eps.
__global__ __launch_bounds__(256) void k_scan(const float* __restrict__ obs,
                                              const float* __restrict__ Beta) {
    extern __shared__ __align__(16) char sm[];
    float* obs_s = (float*)sm;                       // 256 chunks x 68 floats
    uint4* out_s = (uint4*)(sm + 256 * 68 * 4);      // 256 chunks x 8 uint4 (swizzled)
    float* psr   = (float*)(sm + 256 * 68 * 4 + 256 * 8 * 16);  // 8 floats

    const int tid = threadIdx.x;
    const int k   = blockIdx.x >> 2;
    const int qtr = blockIdx.x & 3;
    if (blockIdx.x == 0 && tid == 0) { g_ll = 0.0; g_done = 0; }
    const float4* orow4 = (const float4*)(obs + (size_t)k * Ndim) + qtr * 4096;

    // ---- stage 64KB of obs (quarter row), coalesced, into chunk-padded smem
    #pragma unroll
    for (int i = 0; i < 16; ++i) {
        int idx = i * 256 + tid;             // float4 id, 0..4095
        float4 v = __ldg(orow4 + idx);
        int c = idx >> 4, w = idx & 15;
        *(float4*)&obs_s[c * 68 + w * 4] = v;
    }
    __syncthreads();

    const float decay = __expf(-Beta[k]);

    // ---- warmup over obs[n0-32 .. n0-1]  (last value becomes `prev`)
    float h = 0.f, prev = 0.f;
    if (tid > 0) {
        const float* wsrc = &obs_s[(tid - 1) * 68 + 32];
        #pragma unroll
        for (int j = 0; j < 8; ++j) {
            float4 f = *(const float4*)(wsrc + j * 4);
            h = __fmaf_rn(decay, h, f.x * decay);
            h = __fmaf_rn(decay, h, f.y * decay);
            h = __fmaf_rn(decay, h, f.z * decay);
            if (j < 7) h = __fmaf_rn(decay, h, f.w * decay); else prev = f.w;
        }
    } else if (qtr > 0) {
        const float4* g = (const float4*)(obs + (size_t)k * Ndim + qtr * 16384 - 32);
        #pragma unroll
        for (int j = 0; j < 8; ++j) {
            float4 f = __ldg(g + j);
            h = __fmaf_rn(decay, h, f.x * decay);
            h = __fmaf_rn(decay, h, f.y * decay);
            h = __fmaf_rn(decay, h, f.z * decay);
            if (j < 7) h = __fmaf_rn(decay, h, f.w * decay); else prev = f.w;
        }
    }
    // qtr==0 && tid==0: h=0, prev=0 -> H(0)=0 exactly as reference requires.

    // ---- recurrence over this thread's 64-step chunk (== one tile row)
    float sum = 0.f;
    const float* src = &obs_s[tid * 68];
    #pragma unroll
    for (int q = 0; q < 8; ++q) {
        float4 a = *(const float4*)(src + q * 8);
        float4 b = *(const float4*)(src + q * 8 + 4);
        float v[8] = {a.x, a.y, a.z, a.w, b.x, b.y, b.z, b.w};
        __nv_bfloat162 p[4];
        #pragma unroll
        for (int r = 0; r < 8; r += 2) {
            h = __fmaf_rn(decay, h, prev * decay);  float h0 = h;
            h = __fmaf_rn(decay, h, v[r] * decay);  float h1 = h;
            prev = v[r + 1];
            p[r >> 1] = __floats2bfloat162_rn(h0, h1);
            sum += v[r] + v[r + 1];
        }
        out_s[tid * 8 + (q ^ (tid & 7))] = *(uint4*)p;   // XOR-swizzled store
    }

    // ---- block-reduce quarter-row sum -> one psum per block
    #pragma unroll
    for (int o = 16; o > 0; o >>= 1)
        sum += __shfl_down_sync(0xffffffffu, sum, o);
    if ((tid & 31) == 0) psr[tid >> 5] = sum;
    __syncthreads();
    if (tid == 0) {
        float s = 0.f;
        #pragma unroll
        for (int i = 0; i < 8; ++i) s += psr[i];
        g_psum[k * 4 + qtr] = s;
    }

    // ---- cooperative coalesced store into [tile64][k][64] blocks
    uint4* g4 = (uint4*)g_S;
    #pragma unroll
    for (int j = 0; j < 8; ++j) {
        int idx = j * 256 + tid;             // 0..2047
        int gc = idx >> 3, qq = idx & 7;
        uint4 v = out_s[gc * 8 + (qq ^ (gc & 7))];
        int tile = qtr * 256 + gc;
        g4[((size_t)tile * Kdim + k) * 8 + qq] = v;
    }
}

// ---------------- mma / ldmatrix helpers -------------------------------------
__device__ __forceinline__ void mma16816(float* c, const unsigned* a, unsigned b0, unsigned b1) {
    asm volatile(
        "mma.sync.aligned.m16n8k16.row.col.f32.bf16.bf16.f32 "
        "{%0,%1,%2,%3}, {%4,%5,%6,%7}, {%8,%9}, {%0,%1,%2,%3};\n"
        : "+f"(c[0]), "+f"(c[1]), "+f"(c[2]), "+f"(c[3])
        : "r"(a[0]), "r"(a[1]), "r"(a[2]), "r"(a[3]), "r"(b0), "r"(b1));
}
__device__ __forceinline__ void ldmx4(unsigned& r0, unsigned& r1, unsigned& r2, unsigned& r3,
                                      unsigned addr) {
    asm volatile("ldmatrix.sync.aligned.m8n8.x4.shared.b16 {%0,%1,%2,%3}, [%4];"
                 : "=r"(r0), "=r"(r1), "=r"(r2), "=r"(r3) : "r"(addr));
}
__device__ __forceinline__ void ldmx4t(unsigned& r0, unsigned& r1, unsigned& r2, unsigned& r3,
                                       unsigned addr) {
    asm volatile("ldmatrix.sync.aligned.m8n8.x4.trans.shared.b16 {%0,%1,%2,%3}, [%4];"
                 : "=r"(r0), "=r"(r1), "=r"(r2), "=r"(r3) : "r"(addr));
}
__device__ __forceinline__ void cpa16(unsigned dst, const void* src) {
    asm volatile("cp.async.cg.shared.global [%0], [%1], 16;" :: "r"(dst), "l"(src));
}

// smem byte offsets for k_gemm
#define SOFF_A   0               // 256 x 512B (Alpha*Beta bf16, seg-XOR swizzled)
#define SOFF_S0  131072          // S tile buf 0: 256 k-rows x 128B (64 t bf16)
#define SOFF_S1  163840          // S tile buf 1
#define SOFF_BB  196608          // dedicated 32KB f32 bounce [128 j][64 t]
#define SOFF_MU  229376
#define SOFF_RED 230400          // 32 doubles
#define SMEM_TOT 230656

// ---------------- fused GEMM (lam1 = softplus((Alpha*Beta) @ H)) + epilogue --
// 1024 threads, 32 warps as 8 j-warps (32 rows) x 4 t-warps (16 cols): LDSM
// count per warp 48 (was 72) for the same 64 HMMA. Next S tile's cp.async is
// issued at loop top into the idle buffer -> DRAM latency hidden behind the
// whole MMA+epilogue. Dedicated bounce buffer; 4 syncs/tile. Mu0 computed
// per-CTA from g_psum (k_mu0 kernel deleted).
__global__ __launch_bounds__(1024, 1) void k_gemm(
    const float* __restrict__ obs,
    const float* __restrict__ Alpha,
    const float* __restrict__ Beta,
    float* __restrict__ out)
{
    extern __shared__ __align__(16) char smem[];
    const unsigned su = (unsigned)__cvta_generic_to_shared(smem);
    float*  Mu0s = (float*)(smem + SOFF_MU);
    double* red  = (double*)(smem + SOFF_RED);

    const int tid = threadIdx.x, wid = tid >> 5, lane = tid & 31;
    const int wj = wid & 7;                 // 8 warps x 32 j rows
    const int wt = wid >> 3;                // 4 warps x 16 t cols
    const int jsw = lane & 7, subk = lane >> 4;
    const int lg = lane >> 2, lm = lane & 3;

    // ---- prologue: prefetch tile(blockIdx) -> buf0
    {
        const char* src = (const char*)g_S + (size_t)blockIdx.x * 32768;
        #pragma unroll
        for (int i = 0; i < 2; ++i) {
            int idx = tid + i * 1024;       // 0..2047
            int k = idx >> 3, s = idx & 7;
            cpa16(su + SOFF_S0 + k * 128 + ((s ^ (k & 7)) << 4), src + idx * 16);
        }
        asm volatile("cp.async.commit_group;");
    }

    // ---- stage Alpha*Beta -> swizzled bf16 smem [j][k] (rows 512B)
    {
        const float4* A4 = (const float4*)Alpha;
        const float4* B4 = (const float4*)Beta;
        #pragma unroll
        for (int ii = 0; ii < 8; ++ii) {
            int idx = tid + ii * 1024;      // 16B chunks, 0..8191
            int j = idx >> 5, s = idx & 31;
            float4 v0 = A4[j * 64 + s * 2];
            float4 v1 = A4[j * 64 + s * 2 + 1];
            float4 b0 = __ldg(B4 + s * 2);
            float4 b1 = __ldg(B4 + s * 2 + 1);
            __nv_bfloat162 pk[4];
            pk[0] = __floats2bfloat162_rn(v0.x * b0.x, v0.y * b0.y);
            pk[1] = __floats2bfloat162_rn(v0.z * b0.z, v0.w * b0.w);
            pk[2] = __floats2bfloat162_rn(v1.x * b1.x, v1.y * b1.y);
            pk[3] = __floats2bfloat162_rn(v1.z * b1.z, v1.w * b1.w);
            int phys = (s & 24) | ((s & 7) ^ (j & 7));
            *(uint4*)(smem + SOFF_A + j * 512 + phys * 16) = *(uint4*)pk;
        }
        // Mu0 per-CTA from g_psum (written by k_scan; visible across launch)
        if (tid < 256) {
            float4 ps = *(const float4*)(g_psum + tid * 4);
            Mu0s[tid] = ((ps.x + ps.y) + (ps.z + ps.w)) * (1.0f / Ndim) * 0.1f + 0.01f;
        }
    }

    // ---- precomputed lane addresses
    unsigned ja[2];
    #pragma unroll
    for (int mf = 0; mf < 2; ++mf) {
        int jrow = wj * 32 + mf * 16 + (lane & 8) + jsw;
        ja[mf] = su + SOFF_A + jrow * 512;
    }
    // B: two t-octets per warp; lanes are k-rows; phys seg = toct ^ (k&7)
    const unsigned boct0 = (unsigned)(lane * 128 + (((wt * 2 + 0) ^ jsw) << 4));
    const unsigned boct1 = (unsigned)(lane * 128 + (((wt * 2 + 1) ^ jsw) << 4));

    float*  lams0 = out + 1;
    float*  lams1 = out + 1 + (size_t)Kdim * Ndim;
    float*  Bf  = (float*)(smem + SOFF_BB);
    float2* Bf2 = (float2*)Bf;

    double lsum = 0.0;
    int p = 0;

    for (int tile = blockIdx.x; tile < NT; tile += gridDim.x, p ^= 1) {
        // ---- issue next tile's load into the idle buffer FIRST (depth-2)
        {
            int nxt = tile + gridDim.x;
            if (nxt < NT) {
                const char* src = (const char*)g_S + (size_t)nxt * 32768;
                unsigned dbase = su + (p ? SOFF_S0 : SOFF_S1);
                #pragma unroll
                for (int i = 0; i < 2; ++i) {
                    int idx = tid + i * 1024;
                    int k = idx >> 3, s = idx & 7;
                    cpa16(dbase + k * 128 + ((s ^ (k & 7)) << 4), src + idx * 16);
                }
            }
            asm volatile("cp.async.commit_group;");
        }
        asm volatile("cp.async.wait_group 1;" ::: "memory");   // current tile ready
        __syncthreads();   // buf[p] visible; BB free (prev epilogue done)

        // ---- MMA
        float acc[2][2][4];
        #pragma unroll
        for (int a = 0; a < 2; ++a)
            #pragma unroll
            for (int b = 0; b < 2; ++b)
                #pragma unroll
                for (int d = 0; d < 4; ++d) acc[a][b][d] = 0.f;

        const unsigned bufb = su + (p ? SOFF_S1 : SOFF_S0);
        #pragma unroll
        for (int ks2 = 0; ks2 < 8; ++ks2) {
            unsigned c0, c1, c2, c3, d0, d1, d2, d3;
            ldmx4t(c0, c1, c2, c3, bufb + boct0 + ks2 * 4096);
            ldmx4t(d0, d1, d2, d3, bufb + boct1 + ks2 * 4096);
            #pragma unroll
            for (int hh = 0; hh < 2; ++hh) {
                const int sA = (ks2 * 2 + hh) * 2 + subk;
                const unsigned aoff = (unsigned)(((sA & 24) | ((sA & 7) ^ jsw)) << 4);
                const unsigned cx = hh ? c2 : c0, cy = hh ? c3 : c1;
                const unsigned dx = hh ? d2 : d0, dy = hh ? d3 : d1;
                #pragma unroll
                for (int mf = 0; mf < 2; ++mf) {
                    unsigned a[4];
                    ldmx4(a[0], a[1], a[2], a[3], ja[mf] + aoff);
                    mma16816(acc[mf][0], a, cx, cy);
                    mma16816(acc[mf][1], a, dx, dy);
                }
            }
        }

        // ---- epilogue: 2 j-slices of 128 rows through dedicated bounce
        const int n0 = tile * TT;
        #pragma unroll
        for (int s = 0; s < 2; ++s) {
            if ((wj >> 2) == s) {
                #pragma unroll
                for (int mf = 0; mf < 2; ++mf)
                    #pragma unroll
                    for (int half = 0; half < 2; ++half) {
                        const int jl = (wj & 3) * 32 + mf * 16 + lg + half * 8;
                        #pragma unroll
                        for (int nf = 0; nf < 2; ++nf) {
                            const int gsw = (wt * 2 + nf) ^ (jl & 7);
                            Bf2[jl * 32 + gsw * 4 + lm] =
                                make_float2(acc[mf][nf][half * 2], acc[mf][nf][half * 2 + 1]);
                        }
                    }
            }
            __syncthreads();   // bounce slice visible

            float fsum = 0.f;
            #pragma unroll
            for (int rr = 0; rr < 4; ++rr) {
                const int jl = wid * 4 + rr;
                const int jg = s * 128 + jl;
                const float mu = Mu0s[jg];
                const size_t rowbase = (size_t)jg * Ndim + n0;
                #pragma unroll
                for (int pass = 0; pass < 2; ++pass) {
                    const int tof = pass * 32 + lane;
                    float z = Bf[jl * 64 + (((tof >> 3) ^ (jl & 7)) << 3) + (tof & 7)];
                    float lam = z + __logf(1.f + __expf(-z));   // softplus, z>=0
                    if (n0 + tof == 0) lam = 0.f;   // reference: lams1[:,0] = 0
                    const size_t base = rowbase + tof;
                    lams1[base] = lam;
                    lams0[base] = mu;
                    float o = __ldg(obs + base);
                    fsum += o * __logf(mu + lam + 1e-5f) - mu - lam;
                }
            }
            lsum += (double)fsum;
            if (s == 0) __syncthreads();   // slice-0 reads done before slice-1 writes
            // s==1: loop-top sync of next tile protects BB reuse
        }
    }
    asm volatile("cp.async.wait_group 0;" ::: "memory");   // drain tail prefetch

    // ---- loglik reduction + folded final write
    #pragma unroll
    for (int o = 16; o > 0; o >>= 1)
        lsum += __shfl_down_sync(0xffffffffu, lsum, o);
    if (lane == 0) red[wid] = lsum;
    __syncthreads();
    if (tid == 0) {
        double s = 0.0;
        #pragma unroll
        for (int i = 0; i < 32; ++i) s += red[i];
        atomicAdd(&g_ll, s);
        __threadfence();
        int done = atomicAdd(&g_done, 1);
        if (done == gridDim.x - 1) {
            out[0] = (float)atomicAdd(&g_ll, 0.0);   // coherent read of final sum
            g_done = 0;                              // reset for next graph replay
        }
    }
}

// ---------------- launch ------------------------------------------------------
extern "C" void kernel_launch(void* const* d_in, const int* in_sizes, int n_in,
                              void* d_out, int out_size) {
    const float* obs   = (const float*)d_in[0];
    const float* Beta  = (const float*)d_in[1];
    const float* Alpha = (const float*)d_in[2];
    float* out = (float*)d_out;

    const int scan_smem = 256 * 68 * 4 + 256 * 8 * 16 + 64 * 4;   // 102656 B
    cudaFuncSetAttribute(k_scan, cudaFuncAttributeMaxDynamicSharedMemorySize, scan_smem);
    k_scan<<<Kdim * 4, 256, scan_smem>>>(obs, Beta);

    cudaFuncSetAttribute(k_gemm, cudaFuncAttributeMaxDynamicSharedMemorySize, SMEM_TOT);
    int nsm = 148;
    cudaDeviceGetAttribute(&nsm, cudaDevAttrMultiProcessorCount, 0);
    k_gemm<<<nsm, 1024, SMEM_TOT>>>(obs, Alpha, Beta, out);
}

// round 12
// speedup vs baseline: 1.6190x; 1.0488x over previous
#include <cuda_runtime.h>
#include <cuda_bf16.h>
#include <cstdint>

#define Kdim 256
#define Ndim 65536
#define TT   64                  // GEMM time-tile width
#define NT   (Ndim / TT)         // 1024

// ---------------- scratch (static device globals; no allocation) -------------
__device__ __nv_bfloat16 g_S[(size_t)Kdim * Ndim];   // [tile64][k][64] bf16
__device__ float  g_psum[Kdim * 4];
__device__ double g_ll;
__device__ int    g_done;

// ---------------- scan: truncated exponential-kernel recursion ---------------
// H(i) = decay*(H(i-1)+obs[k][i-1]) == fma(decay, H, decay*obs) -> 4cyc chain.
// decay <= e^-1 -> 32-step warmup error ~1e-14 << bf16 eps.
// smem = one 64KB seg-XOR-swizzled obs block (256 chunks x 256B). The bf16
// output is buffered in registers and written IN-PLACE over the consumed obs
// rows -> 64.3KB/CTA -> 3 CTAs/SM (24 warps) to hide the serial FMA chain.
__global__ __launch_bounds__(256, 3) void k_scan(const float* __restrict__ obs,
                                                 const float* __restrict__ Beta) {
    extern __shared__ __align__(16) char sm[];
    float* psr = (float*)(sm + 65536);               // 8 floats

    const int tid = threadIdx.x;
    const int k   = blockIdx.x >> 2;
    const int qtr = blockIdx.x & 3;
    const int x   = tid & 15;                        // row swizzle key
    if (blockIdx.x == 0 && tid == 0) { g_ll = 0.0; g_done = 0; }
    const float4* orow4 = (const float4*)(obs + (size_t)k * Ndim) + qtr * 4096;

    // ---- stage 64KB of obs (quarter row), coalesced, seg-XOR swizzled rows
    #pragma unroll
    for (int i = 0; i < 16; ++i) {
        int idx = i * 256 + tid;             // float4 id, 0..4095
        float4 v = __ldg(orow4 + idx);
        int c = idx >> 4, s = idx & 15;
        *(float4*)(sm + c * 256 + ((s ^ (c & 15)) << 4)) = v;
    }
    __syncthreads();

    const float decay = __expf(-Beta[k]);

    // ---- warmup over obs[n0-32 .. n0-1] (row tid-1, segs 8..15)
    float h = 0.f, prev = 0.f;
    if (tid > 0) {
        const char* wrow = sm + (tid - 1) * 256;
        const int wx = (tid - 1) & 15;
        #pragma unroll
        for (int j = 0; j < 8; ++j) {
            float4 f = *(const float4*)(wrow + (((8 + j) ^ wx) << 4));
            h = __fmaf_rn(decay, h, f.x * decay);
            h = __fmaf_rn(decay, h, f.y * decay);
            h = __fmaf_rn(decay, h, f.z * decay);
            if (j < 7) h = __fmaf_rn(decay, h, f.w * decay); else prev = f.w;
        }
    } else if (qtr > 0) {
        const float4* g = (const float4*)(obs + (size_t)k * Ndim + qtr * 16384 - 32);
        #pragma unroll
        for (int j = 0; j < 8; ++j) {
            float4 f = __ldg(g + j);
            h = __fmaf_rn(decay, h, f.x * decay);
            h = __fmaf_rn(decay, h, f.y * decay);
            h = __fmaf_rn(decay, h, f.z * decay);
            if (j < 7) h = __fmaf_rn(decay, h, f.w * decay); else prev = f.w;
        }
    }
    // qtr==0 && tid==0: h=0, prev=0 -> H(0)=0 exactly as reference requires.

    // ---- recurrence over this thread's 64-step chunk; output kept in regs
    float sum = 0.f;
    uint4 po[8];
    const char* row = sm + tid * 256;
    #pragma unroll
    for (int q = 0; q < 8; ++q) {
        float4 a = *(const float4*)(row + (((2 * q)     ^ x) << 4));
        float4 b = *(const float4*)(row + (((2 * q + 1) ^ x) << 4));
        float v[8] = {a.x, a.y, a.z, a.w, b.x, b.y, b.z, b.w};
        __nv_bfloat162 p[4];
        #pragma unroll
        for (int r = 0; r < 8; r += 2) {
            h = __fmaf_rn(decay, h, prev * decay);  float h0 = h;
            h = __fmaf_rn(decay, h, v[r] * decay);  float h1 = h;
            prev = v[r + 1];
            p[r >> 1] = __floats2bfloat162_rn(h0, h1);
            sum += v[r] + v[r + 1];
        }
        po[q] = *(uint4*)p;
    }

    // ---- block-reduce quarter-row sum -> one psum per block
    #pragma unroll
    for (int o = 16; o > 0; o >>= 1)
        sum += __shfl_down_sync(0xffffffffu, sum, o);
    if ((tid & 31) == 0) psr[tid >> 5] = sum;
    __syncthreads();                         // also: all obs reads complete
    if (tid == 0) {
        float s = 0.f;
        #pragma unroll
        for (int i = 0; i < 8; ++i) s += psr[i];
        g_psum[k * 4 + qtr] = s;
    }

    // ---- write bf16 output in-place over own (fully consumed) obs row
    #pragma unroll
    for (int q = 0; q < 8; ++q)
        *(uint4*)(sm + tid * 256 + ((q ^ x) << 4)) = po[q];
    __syncthreads();

    // ---- cooperative coalesced store into [tile64][k][64] blocks
    uint4* g4 = (uint4*)g_S;
    #pragma unroll
    for (int j = 0; j < 8; ++j) {
        int idx = j * 256 + tid;             // 0..2047
        int gc = idx >> 3, qq = idx & 7;
        uint4 v = *(const uint4*)(sm + gc * 256 + ((qq ^ (gc & 15)) << 4));
        int tile = qtr * 256 + gc;
        g4[((size_t)tile * Kdim + k) * 8 + qq] = v;
    }
}

// ---------------- mma / ldmatrix helpers -------------------------------------
__device__ __forceinline__ void mma16816(float* c, const unsigned* a, unsigned b0, unsigned b1) {
    asm volatile(
        "mma.sync.aligned.m16n8k16.row.col.f32.bf16.bf16.f32 "
        "{%0,%1,%2,%3}, {%4,%5,%6,%7}, {%8,%9}, {%0,%1,%2,%3};\n"
        : "+f"(c[0]), "+f"(c[1]), "+f"(c[2]), "+f"(c[3])
        : "r"(a[0]), "r"(a[1]), "r"(a[2]), "r"(a[3]), "r"(b0), "r"(b1));
}
__device__ __forceinline__ void ldmx4(unsigned& r0, unsigned& r1, unsigned& r2, unsigned& r3,
                                      unsigned addr) {
    asm volatile("ldmatrix.sync.aligned.m8n8.x4.shared.b16 {%0,%1,%2,%3}, [%4];"
                 : "=r"(r0), "=r"(r1), "=r"(r2), "=r"(r3) : "r"(addr));
}
__device__ __forceinline__ void ldmx4t(unsigned& r0, unsigned& r1, unsigned& r2, unsigned& r3,
                                       unsigned addr) {
    asm volatile("ldmatrix.sync.aligned.m8n8.x4.trans.shared.b16 {%0,%1,%2,%3}, [%4];"
                 : "=r"(r0), "=r"(r1), "=r"(r2), "=r"(r3) : "r"(addr));
}
__device__ __forceinline__ void cpa16(unsigned dst, const void* src) {
    asm volatile("cp.async.cg.shared.global [%0], [%1], 16;" :: "r"(dst), "l"(src));
}

// smem byte offsets for k_gemm
#define SOFF_A   0               // 256 x 512B (Alpha*Beta bf16, seg-XOR swizzled)
#define SOFF_S0  131072          // S tile buf 0: 256 k-rows x 128B (64 t bf16)
#define SOFF_S1  163840          // S tile buf 1
#define SOFF_BB  196608          // dedicated 32KB f32 bounce [128 j][64 t]
#define SOFF_MU  229376
#define SOFF_RED 230400          // 32 doubles
#define SMEM_TOT 230656

// ---------------- fused GEMM (lam1 = softplus((Alpha*Beta) @ H)) + epilogue --
// (round-9 proven version: 70.8us, occ 48.6%) 1024 threads, 32 warps as
// 8 j-warps x 4 t-warps; depth-2 cp.async S pipeline; dedicated bounce buffer;
// Mu0 computed per-CTA from g_psum; final scalar folded via completion counter.
__global__ __launch_bounds__(1024, 1) void k_gemm(
    const float* __restrict__ obs,
    const float* __restrict__ Alpha,
    const float* __restrict__ Beta,
    float* __restrict__ out)
{
    extern __shared__ __align__(16) char smem[];
    const unsigned su = (unsigned)__cvta_generic_to_shared(smem);
    float*  Mu0s = (float*)(smem + SOFF_MU);
    double* red  = (double*)(smem + SOFF_RED);

    const int tid = threadIdx.x, wid = tid >> 5, lane = tid & 31;
    const int wj = wid & 7;                 // 8 warps x 32 j rows
    const int wt = wid >> 3;                // 4 warps x 16 t cols
    const int jsw = lane & 7, subk = lane >> 4;
    const int lg = lane >> 2, lm = lane & 3;

    // ---- prologue: prefetch tile(blockIdx) -> buf0
    {
        const char* src = (const char*)g_S + (size_t)blockIdx.x * 32768;
        #pragma unroll
        for (int i = 0; i < 2; ++i) {
            int idx = tid + i * 1024;       // 0..2047
            int k = idx >> 3, s = idx & 7;
            cpa16(su + SOFF_S0 + k * 128 + ((s ^ (k & 7)) << 4), src + idx * 16);
        }
        asm volatile("cp.async.commit_group;");
    }

    // ---- stage Alpha*Beta -> swizzled bf16 smem [j][k] (rows 512B)
    {
        const float4* A4 = (const float4*)Alpha;
        const float4* B4 = (const float4*)Beta;
        #pragma unroll
        for (int ii = 0; ii < 8; ++ii) {
            int idx = tid + ii * 1024;      // 16B chunks, 0..8191
            int j = idx >> 5, s = idx & 31;
            float4 v0 = A4[j * 64 + s * 2];
            float4 v1 = A4[j * 64 + s * 2 + 1];
            float4 b0 = __ldg(B4 + s * 2);
            float4 b1 = __ldg(B4 + s * 2 + 1);
            __nv_bfloat162 pk[4];
            pk[0] = __floats2bfloat162_rn(v0.x * b0.x, v0.y * b0.y);
            pk[1] = __floats2bfloat162_rn(v0.z * b0.z, v0.w * b0.w);
            pk[2] = __floats2bfloat162_rn(v1.x * b1.x, v1.y * b1.y);
            pk[3] = __floats2bfloat162_rn(v1.z * b1.z, v1.w * b1.w);
            int phys = (s & 24) | ((s & 7) ^ (j & 7));
            *(uint4*)(smem + SOFF_A + j * 512 + phys * 16) = *(uint4*)pk;
        }
        // Mu0 per-CTA from g_psum (written by k_scan; visible across launch)
        if (tid < 256) {
            float4 ps = *(const float4*)(g_psum + tid * 4);
            Mu0s[tid] = ((ps.x + ps.y) + (ps.z + ps.w)) * (1.0f / Ndim) * 0.1f + 0.01f;
        }
    }

    // ---- precomputed lane addresses
    unsigned ja[2];
    #pragma unroll
    for (int mf = 0; mf < 2; ++mf) {
        int jrow = wj * 32 + mf * 16 + (lane & 8) + jsw;
        ja[mf] = su + SOFF_A + jrow * 512;
    }
    const unsigned boct0 = (unsigned)(lane * 128 + (((wt * 2 + 0) ^ jsw) << 4));
    const unsigned boct1 = (unsigned)(lane * 128 + (((wt * 2 + 1) ^ jsw) << 4));

    float*  lams0 = out + 1;
    float*  lams1 = out + 1 + (size_t)Kdim * Ndim;
    float*  Bf  = (float*)(smem + SOFF_BB);
    float2* Bf2 = (float2*)Bf;

    double lsum = 0.0;
    int p = 0;

    for (int tile = blockIdx.x; tile < NT; tile += gridDim.x, p ^= 1) {
        // ---- issue next tile's load into the idle buffer FIRST (depth-2)
        {
            int nxt = tile + gridDim.x;
            if (nxt < NT) {
                const char* src = (const char*)g_S + (size_t)nxt * 32768;
                unsigned dbase = su + (p ? SOFF_S0 : SOFF_S1);
                #pragma unroll
                for (int i = 0; i < 2; ++i) {
                    int idx = tid + i * 1024;
                    int k = idx >> 3, s = idx & 7;
                    cpa16(dbase + k * 128 + ((s ^ (k & 7)) << 4), src + idx * 16);
                }
            }
            asm volatile("cp.async.commit_group;");
        }
        asm volatile("cp.async.wait_group 1;" ::: "memory");   // current tile ready
        __syncthreads();   // buf[p] visible; BB free (prev epilogue done)

        // ---- MMA
        float acc[2][2][4];
        #pragma unroll
        for (int a = 0; a < 2; ++a)
            #pragma unroll
            for (int b = 0; b < 2; ++b)
                #pragma unroll
                for (int d = 0; d < 4; ++d) acc[a][b][d] = 0.f;

        const unsigned bufb = su + (p ? SOFF_S1 : SOFF_S0);
        #pragma unroll
        for (int ks2 = 0; ks2 < 8; ++ks2) {
            unsigned c0, c1, c2, c3, d0, d1, d2, d3;
            ldmx4t(c0, c1, c2, c3, bufb + boct0 + ks2 * 4096);
            ldmx4t(d0, d1, d2, d3, bufb + boct1 + ks2 * 4096);
            #pragma unroll
            for (int hh = 0; hh < 2; ++hh) {
                const int sA = (ks2 * 2 + hh) * 2 + subk;
                const unsigned aoff = (unsigned)(((sA & 24) | ((sA & 7) ^ jsw)) << 4);
                const unsigned cx = hh ? c2 : c0, cy = hh ? c3 : c1;
                const unsigned dx = hh ? d2 : d0, dy = hh ? d3 : d1;
                #pragma unroll
                for (int mf = 0; mf < 2; ++mf) {
                    unsigned a[4];
                    ldmx4(a[0], a[1], a[2], a[3], ja[mf] + aoff);
                    mma16816(acc[mf][0], a, cx, cy);
                    mma16816(acc[mf][1], a, dx, dy);
                }
            }
        }

        // ---- epilogue: 2 j-slices of 128 rows through dedicated bounce
        const int n0 = tile * TT;
        #pragma unroll
        for (int s = 0; s < 2; ++s) {
            if ((wj >> 2) == s) {
                #pragma unroll
                for (int mf = 0; mf < 2; ++mf)
                    #pragma unroll
                    for (int half = 0; half < 2; ++half) {
                        const int jl = (wj & 3) * 32 + mf * 16 + lg + half * 8;
                        #pragma unroll
                        for (int nf = 0; nf < 2; ++nf) {
                            const int gsw = (wt * 2 + nf) ^ (jl & 7);
                            Bf2[jl * 32 + gsw * 4 + lm] =
                                make_float2(acc[mf][nf][half * 2], acc[mf][nf][half * 2 + 1]);
                        }
                    }
            }
            __syncthreads();   // bounce slice visible

            float fsum = 0.f;
            #pragma unroll
            for (int rr = 0; rr < 4; ++rr) {
                const int jl = wid * 4 + rr;
                const int jg = s * 128 + jl;
                const float mu = Mu0s[jg];
                const size_t rowbase = (size_t)jg * Ndim + n0;
                #pragma unroll
                for (int pass = 0; pass < 2; ++pass) {
                    const int tof = pass * 32 + lane;
                    float z = Bf[jl * 64 + (((tof >> 3) ^ (jl & 7)) << 3) + (tof & 7)];
                    float lam = z + __logf(1.f + __expf(-z));   // softplus, z>=0
                    if (n0 + tof == 0) lam = 0.f;   // reference: lams1[:,0] = 0
                    const size_t base = rowbase + tof;
                    lams1[base] = lam;
                    lams0[base] = mu;
                    float o = __ldg(obs + base);
                    fsum += o * __logf(mu + lam + 1e-5f) - mu - lam;
                }
            }
            lsum += (double)fsum;
            if (s == 0) __syncthreads();   // slice-0 reads done before slice-1 writes
            // s==1: loop-top sync of next tile protects BB reuse
        }
    }
    asm volatile("cp.async.wait_group 0;" ::: "memory");   // drain tail prefetch

    // ---- loglik reduction + folded final write
    #pragma unroll
    for (int o = 16; o > 0; o >>= 1)
        lsum += __shfl_down_sync(0xffffffffu, lsum, o);
    if (lane == 0) red[wid] = lsum;
    __syncthreads();
    if (tid == 0) {
        double s = 0.0;
        #pragma unroll
        for (int i = 0; i < 32; ++i) s += red[i];
        atomicAdd(&g_ll, s);
        __threadfence();
        int done = atomicAdd(&g_done, 1);
        if (done == gridDim.x - 1) {
            out[0] = (float)atomicAdd(&g_ll, 0.0);   // coherent read of final sum
            g_done = 0;                              // reset for next graph replay
        }
    }
}

// ---------------- launch ------------------------------------------------------
extern "C" void kernel_launch(void* const* d_in, const int* in_sizes, int n_in,
                              void* d_out, int out_size) {
    const float* obs   = (const float*)d_in[0];
    const float* Beta  = (const float*)d_in[1];
    const float* Alpha = (const float*)d_in[2];
    float* out = (float*)d_out;

    const int scan_smem = 65536 + 64;   // 64KB obs block + psum scratch
    cudaFuncSetAttribute(k_scan, cudaFuncAttributeMaxDynamicSharedMemorySize, scan_smem);
    k_scan<<<Kdim * 4, 256, scan_smem>>>(obs, Beta);

    cudaFuncSetAttribute(k_gemm, cudaFuncAttributeMaxDynamicSharedMemorySize, SMEM_TOT);
    int nsm = 148;
    cudaDeviceGetAttribute(&nsm, cudaDevAttrMultiProcessorCount, 0);
    k_gemm<<<nsm, 1024, SMEM_TOT>>>(obs, Alpha, Beta, out);
}

// round 13
// speedup vs baseline: 1.6685x; 1.0306x over previous
#include <cuda_runtime.h>
#include <cuda_bf16.h>
#include <cstdint>

#define Kdim 256
#define Ndim 65536
#define TT   64                  // GEMM time-tile width
#define NT   (Ndim / TT)         // 1024

// ---------------- scratch (static device globals; no allocation) -------------
__device__ __nv_bfloat16 g_S[(size_t)Kdim * Ndim];   // [tile64][k][64] bf16
__device__ float  g_psum[Kdim * 4];
__device__ double g_ll;
__device__ int    g_done;

__device__ __forceinline__ void cpa16(unsigned dst, const void* src) {
    asm volatile("cp.async.cg.shared.global [%0], [%1], 16;" :: "r"(dst), "l"(src));
}

// ---------------- scan: truncated exponential-kernel recursion ---------------
// H(i) = decay*(H(i-1)+obs[k][i-1]) == fma(decay, H, decay*obs) -> 4cyc chain.
// decay <= e^-1 -> 32-step warmup error ~1e-14 << bf16 eps.
// cp.async staging; bf16 output written IN-PLACE over the consumed obs row
// (logical segs 0..7 written, neighbor warmup reads only segs 8..15) ->
// 64.1KB smem, low regs -> 3 CTAs/SM.
__global__ __launch_bounds__(256, 3) void k_scan(const float* __restrict__ obs,
                                                 const float* __restrict__ Beta) {
    extern __shared__ __align__(16) char sm[];
    const unsigned su = (unsigned)__cvta_generic_to_shared(sm);
    float* psr = (float*)(sm + 65536);               // 8 floats

    const int tid = threadIdx.x;
    const int k   = blockIdx.x >> 2;
    const int qtr = blockIdx.x & 3;
    const int x   = tid & 15;                        // row swizzle key
    if (blockIdx.x == 0 && tid == 0) { g_ll = 0.0; g_done = 0; }
    const float4* orow4 = (const float4*)(obs + (size_t)k * Ndim) + qtr * 4096;

    // ---- stage 64KB of obs (quarter row) via cp.async, seg-XOR swizzled rows
    #pragma unroll
    for (int i = 0; i < 16; ++i) {
        int idx = i * 256 + tid;             // float4 id, 0..4095
        int c = idx >> 4, s = idx & 15;
        cpa16(su + c * 256 + ((s ^ (c & 15)) << 4), orow4 + idx);
    }
    asm volatile("cp.async.commit_group;");
    asm volatile("cp.async.wait_group 0;" ::: "memory");
    __syncthreads();

    const float decay = __expf(-Beta[k]);

    // ---- warmup over obs[n0-32 .. n0-1] (neighbor row, logical segs 8..15)
    float h = 0.f, prev = 0.f;
    if (tid > 0) {
        const char* wrow = sm + (tid - 1) * 256;
        const int wx = (tid - 1) & 15;
        #pragma unroll
        for (int j = 0; j < 8; ++j) {
            float4 f = *(const float4*)(wrow + (((8 + j) ^ wx) << 4));
            h = __fmaf_rn(decay, h, f.x * decay);
            h = __fmaf_rn(decay, h, f.y * decay);
            h = __fmaf_rn(decay, h, f.z * decay);
            if (j < 7) h = __fmaf_rn(decay, h, f.w * decay); else prev = f.w;
        }
    } else if (qtr > 0) {
        const float4* g = (const float4*)(obs + (size_t)k * Ndim + qtr * 16384 - 32);
        #pragma unroll
        for (int j = 0; j < 8; ++j) {
            float4 f = __ldg(g + j);
            h = __fmaf_rn(decay, h, f.x * decay);
            h = __fmaf_rn(decay, h, f.y * decay);
            h = __fmaf_rn(decay, h, f.z * decay);
            if (j < 7) h = __fmaf_rn(decay, h, f.w * decay); else prev = f.w;
        }
    }
    // qtr==0 && tid==0: h=0, prev=0 -> H(0)=0 exactly as reference requires.

    // ---- recurrence over this thread's 64-step chunk; in-place packed output
    float sum = 0.f;
    char* row = sm + tid * 256;
    #pragma unroll
    for (int q = 0; q < 8; ++q) {
        float4 a = *(const float4*)(row + (((2 * q)     ^ x) << 4));
        float4 b = *(const float4*)(row + (((2 * q + 1) ^ x) << 4));
        float v[8] = {a.x, a.y, a.z, a.w, b.x, b.y, b.z, b.w};
        __nv_bfloat162 p[4];
        #pragma unroll
        for (int r = 0; r < 8; r += 2) {
            h = __fmaf_rn(decay, h, prev * decay);  float h0 = h;
            h = __fmaf_rn(decay, h, v[r] * decay);  float h1 = h;
            prev = v[r + 1];
            p[r >> 1] = __floats2bfloat162_rn(h0, h1);
            sum += v[r] + v[r + 1];
        }
        *(uint4*)(row + ((q ^ x) << 4)) = *(uint4*)p;   // logical seg q (< 2q+2)
    }

    // ---- block-reduce quarter-row sum -> one psum per block
    #pragma unroll
    for (int o = 16; o > 0; o >>= 1)
        sum += __shfl_down_sync(0xffffffffu, sum, o);
    if ((tid & 31) == 0) psr[tid >> 5] = sum;
    __syncthreads();                         // all rows packed & reads done
    if (tid == 0) {
        float s = 0.f;
        #pragma unroll
        for (int i = 0; i < 8; ++i) s += psr[i];
        g_psum[k * 4 + qtr] = s;
    }

    // ---- cooperative coalesced store into [tile64][k][64] blocks
    uint4* g4 = (uint4*)g_S;
    #pragma unroll
    for (int j = 0; j < 8; ++j) {
        int idx = j * 256 + tid;             // 0..2047
        int gc = idx >> 3, qq = idx & 7;
        uint4 v = *(const uint4*)(sm + gc * 256 + ((qq ^ (gc & 15)) << 4));
        int tile = qtr * 256 + gc;
        g4[((size_t)tile * Kdim + k) * 8 + qq] = v;
    }
}

// ---------------- mma / ldmatrix helpers -------------------------------------
__device__ __forceinline__ void mma16816(float* c, const unsigned* a, unsigned b0, unsigned b1) {
    asm volatile(
        "mma.sync.aligned.m16n8k16.row.col.f32.bf16.bf16.f32 "
        "{%0,%1,%2,%3}, {%4,%5,%6,%7}, {%8,%9}, {%0,%1,%2,%3};\n"
        : "+f"(c[0]), "+f"(c[1]), "+f"(c[2]), "+f"(c[3])
        : "r"(a[0]), "r"(a[1]), "r"(a[2]), "r"(a[3]), "r"(b0), "r"(b1));
}
__device__ __forceinline__ void ldmx4(unsigned& r0, unsigned& r1, unsigned& r2, unsigned& r3,
                                      unsigned addr) {
    asm volatile("ldmatrix.sync.aligned.m8n8.x4.shared.b16 {%0,%1,%2,%3}, [%4];"
                 : "=r"(r0), "=r"(r1), "=r"(r2), "=r"(r3) : "r"(addr));
}
__device__ __forceinline__ void ldmx4t(unsigned& r0, unsigned& r1, unsigned& r2, unsigned& r3,
                                       unsigned addr) {
    asm volatile("ldmatrix.sync.aligned.m8n8.x4.trans.shared.b16 {%0,%1,%2,%3}, [%4];"
                 : "=r"(r0), "=r"(r1), "=r"(r2), "=r"(r3) : "r"(addr));
}

// smem byte offsets for k_gemm (per 512-thread CTA; 2 CTAs/SM)
#define SOFF_A   0               // 128 rows x 512B (this CTA's Alpha*Beta half)
#define SOFF_S   65536           // S tile: 256 k-rows x 128B (single buffer)
#define SOFF_BB  98304           // 16KB f32 bounce [64 j][64 t]
#define SOFF_MU  114688          // 128 floats
#define SOFF_RED 115200          // 16 doubles
#define SMEM_TOT 115328

// ---------------- fused GEMM (lam1 = softplus((Alpha*Beta) @ H)) + epilogue --
// 512 threads x 2 CTAs/SM, split along j (each CTA owns 128 rows). Independent
// barrier domains self-overlap latency. Single S buffer: next tile's cp.async
// is issued right after the post-MMA sync and hides behind the epilogue.
__global__ __launch_bounds__(512, 2) void k_gemm(
    const float* __restrict__ obs,
    const float* __restrict__ Alpha,
    const float* __restrict__ Beta,
    float* __restrict__ out)
{
    extern __shared__ __align__(16) char smem[];
    const unsigned su = (unsigned)__cvta_generic_to_shared(smem);
    float*  Mu0s = (float*)(smem + SOFF_MU);
    double* red  = (double*)(smem + SOFF_RED);

    const int tid = threadIdx.x, wid = tid >> 5, lane = tid & 31;
    const int jh = blockIdx.x & 1;          // which 128-row j half
    const int wj = wid & 3;                 // 4 warps x 32 j rows
    const int wt = wid >> 2;                // 4 warps x 16 t cols
    const int jsw = lane & 7, subk = lane >> 4;
    const int lg = lane >> 2, lm = lane & 3;
    const int G2 = gridDim.x >> 1;
    const int t0 = blockIdx.x >> 1;

    // ---- prologue: prefetch tile t0 -> S buffer
    {
        const char* src = (const char*)g_S + (size_t)t0 * 32768;
        #pragma unroll
        for (int i = 0; i < 4; ++i) {
            int idx = tid + i * 512;        // 0..2047
            int k = idx >> 3, s = idx & 7;
            cpa16(su + SOFF_S + k * 128 + ((s ^ (k & 7)) << 4), src + idx * 16);
        }
        asm volatile("cp.async.commit_group;");
    }

    // ---- stage this half's Alpha*Beta -> swizzled bf16 smem (rows 512B)
    {
        const float4* A4 = (const float4*)Alpha;
        const float4* B4 = (const float4*)Beta;
        #pragma unroll
        for (int ii = 0; ii < 8; ++ii) {
            int idx = tid + ii * 512;       // 16B chunks, 0..4095
            int jl = idx >> 5, s = idx & 31;
            int jg = jh * 128 + jl;
            float4 v0 = A4[jg * 64 + s * 2];
            float4 v1 = A4[jg * 64 + s * 2 + 1];
            float4 b0 = __ldg(B4 + s * 2);
            float4 b1 = __ldg(B4 + s * 2 + 1);
            __nv_bfloat162 pk[4];
            pk[0] = __floats2bfloat162_rn(v0.x * b0.x, v0.y * b0.y);
            pk[1] = __floats2bfloat162_rn(v0.z * b0.z, v0.w * b0.w);
            pk[2] = __floats2bfloat162_rn(v1.x * b1.x, v1.y * b1.y);
            pk[3] = __floats2bfloat162_rn(v1.z * b1.z, v1.w * b1.w);
            int phys = (s & 24) | ((s & 7) ^ (jl & 7));
            *(uint4*)(smem + SOFF_A + jl * 512 + phys * 16) = *(uint4*)pk;
        }
        if (tid < 128) {
            float4 ps = *(const float4*)(g_psum + (jh * 128 + tid) * 4);
            Mu0s[tid] = ((ps.x + ps.y) + (ps.z + ps.w)) * (1.0f / Ndim) * 0.1f + 0.01f;
        }
    }

    // ---- precomputed lane addresses
    unsigned ja[2];
    #pragma unroll
    for (int mf = 0; mf < 2; ++mf) {
        int jrow = wj * 32 + mf * 16 + (lane & 8) + jsw;   // local 0..127
        ja[mf] = su + SOFF_A + jrow * 512;
    }
    const unsigned boct0 = (unsigned)(lane * 128 + (((wt * 2 + 0) ^ jsw) << 4));
    const unsigned boct1 = (unsigned)(lane * 128 + (((wt * 2 + 1) ^ jsw) << 4));

    float*  lams0 = out + 1;
    float*  lams1 = out + 1 + (size_t)Kdim * Ndim;
    float*  Bf  = (float*)(smem + SOFF_BB);
    float2* Bf2 = (float2*)Bf;

    double lsum = 0.0;

    for (int tile = t0; tile < NT; tile += G2) {
        asm volatile("cp.async.wait_group 0;" ::: "memory");
        __syncthreads();                    // S ready; BB free (prev iter done)

        // ---- MMA
        float acc[2][2][4];
        #pragma unroll
        for (int a = 0; a < 2; ++a)
            #pragma unroll
            for (int b = 0; b < 2; ++b)
                #pragma unroll
                for (int d = 0; d < 4; ++d) acc[a][b][d] = 0.f;

        #pragma unroll
        for (int ks2 = 0; ks2 < 8; ++ks2) {
            unsigned c0, c1, c2, c3, d0, d1, d2, d3;
            ldmx4t(c0, c1, c2, c3, su + SOFF_S + boct0 + ks2 * 4096);
            ldmx4t(d0, d1, d2, d3, su + SOFF_S + boct1 + ks2 * 4096);
            #pragma unroll
            for (int hh = 0; hh < 2; ++hh) {
                const int sA = (ks2 * 2 + hh) * 2 + subk;
                const unsigned aoff = (unsigned)(((sA & 24) | ((sA & 7) ^ jsw)) << 4);
                const unsigned cx = hh ? c2 : c0, cy = hh ? c3 : c1;
                const unsigned dx = hh ? d2 : d0, dy = hh ? d3 : d1;
                #pragma unroll
                for (int mf = 0; mf < 2; ++mf) {
                    unsigned a[4];
                    ldmx4(a[0], a[1], a[2], a[3], ja[mf] + aoff);
                    mma16816(acc[mf][0], a, cx, cy);
                    mma16816(acc[mf][1], a, dx, dy);
                }
            }
        }
        __syncthreads();                    // all MMA reads of S done

        // ---- issue next tile's load into S (hidden behind epilogue)
        {
            int nxt = tile + G2;
            if (nxt < NT) {
                const char* src = (const char*)g_S + (size_t)nxt * 32768;
                #pragma unroll
                for (int i = 0; i < 4; ++i) {
                    int idx = tid + i * 512;
                    int k = idx >> 3, s = idx & 7;
                    cpa16(su + SOFF_S + k * 128 + ((s ^ (k & 7)) << 4), src + idx * 16);
                }
            }
            asm volatile("cp.async.commit_group;");
        }

        // ---- epilogue: 2 j-slices of 64 rows through the bounce
        const int n0 = tile * TT;
        #pragma unroll
        for (int s = 0; s < 2; ++s) {
            if ((wj >> 1) == s) {
                #pragma unroll
                for (int mf = 0; mf < 2; ++mf)
                    #pragma unroll
                    for (int half = 0; half < 2; ++half) {
                        const int jl = (wj & 1) * 32 + mf * 16 + lg + half * 8;
                        #pragma unroll
                        for (int nf = 0; nf < 2; ++nf) {
                            const int gsw = (wt * 2 + nf) ^ (jl & 7);
                            Bf2[jl * 32 + gsw * 4 + lm] =
                                make_float2(acc[mf][nf][half * 2], acc[mf][nf][half * 2 + 1]);
                        }
                    }
            }
            __syncthreads();   // bounce slice visible

            float fsum = 0.f;
            #pragma unroll
            for (int rr = 0; rr < 4; ++rr) {
                const int jl = wid * 4 + rr;              // 0..63
                const int jg = jh * 128 + s * 64 + jl;
                const float mu = Mu0s[s * 64 + jl];
                const size_t rowbase = (size_t)jg * Ndim + n0;
                #pragma unroll
                for (int pass = 0; pass < 2; ++pass) {
                    const int tof = pass * 32 + lane;
                    float z = Bf[jl * 64 + (((tof >> 3) ^ (jl & 7)) << 3) + (tof & 7)];
                    float lam = z + __logf(1.f + __expf(-z));   // softplus, z>=0
                    if (n0 + tof == 0) lam = 0.f;   // reference: lams1[:,0] = 0
                    const size_t base = rowbase + tof;
                    lams1[base] = lam;
                    lams0[base] = mu;
                    float o = __ldg(obs + base);
                    fsum += o * __logf(mu + lam + 1e-5f) - mu - lam;
                }
            }
            lsum += (double)fsum;
            if (s == 0) __syncthreads();   // slice-0 reads done before slice-1 writes
            // s==1: next-iter top sync protects BB reuse
        }
    }
    asm volatile("cp.async.wait_group 0;" ::: "memory");   // drain tail

    // ---- loglik reduction + folded final write
    #pragma unroll
    for (int o = 16; o > 0; o >>= 1)
        lsum += __shfl_down_sync(0xffffffffu, lsum, o);
    if (lane == 0) red[wid] = lsum;
    __syncthreads();
    if (tid == 0) {
        double s = 0.0;
        #pragma unroll
        for (int i = 0; i < 16; ++i) s += red[i];
        atomicAdd(&g_ll, s);
        __threadfence();
        int done = atomicAdd(&g_done, 1);
        if (done == gridDim.x - 1) {
            out[0] = (float)atomicAdd(&g_ll, 0.0);   // coherent read of final sum
            g_done = 0;                              // reset for next graph replay
        }
    }
}

// ---------------- launch ------------------------------------------------------
extern "C" void kernel_launch(void* const* d_in, const int* in_sizes, int n_in,
                              void* d_out, int out_size) {
    const float* obs   = (const float*)d_in[0];
    const float* Beta  = (const float*)d_in[1];
    const float* Alpha = (const float*)d_in[2];
    float* out = (float*)d_out;

    const int scan_smem = 65536 + 64;   // 64KB obs block + psum scratch
    cudaFuncSetAttribute(k_scan, cudaFuncAttributeMaxDynamicSharedMemorySize, scan_smem);
    k_scan<<<Kdim * 4, 256, scan_smem>>>(obs, Beta);

    cudaFuncSetAttribute(k_gemm, cudaFuncAttributeMaxDynamicSharedMemorySize, SMEM_TOT);
    int nsm = 148;
    cudaDeviceGetAttribute(&nsm, cudaDevAttrMultiProcessorCount, 0);
    k_gemm<<<2 * nsm, 512, SMEM_TOT>>>(obs, Alpha, Beta, out);
}